// round 13
// baseline (speedup 1.0000x reference)
#include <cuda_runtime.h>
#include <cuda_fp16.h>
#include <cstdint>

// ---------------------------------------------------------------------------
// MMD loss via mma.sync fp16 gram (fp32 accum) + fused fp32 gaussian epilogue
//   loss = (1/ns^2) * sum_{i,j} s_i s_j K_ij
//   K_ij = u + u^2 + u^4 + u^8 + u^16,  u = 2^(-l2_ij*c4), c4 = log2e/(bw*16)
//   l2_ij = sq_i + sq_j - 2 g_ij ; bandwidth via O(nD) identity.
// Epilogue all-fp32 (R12's half2 pack/unpack cvts were a regression).
// prep+permute fused into one pass (inputs have no bandwidth dependency now);
// c4 computed inline per mmd block. 3 launches total.
// Symmetry: triangular grid (2080 CTAs), off-diagonal tiles weight 2.
// ---------------------------------------------------------------------------

#define NS     4096
#define DDIM   256
#define NTOT   8192
#define BM     128
#define BKC    64
#define NCHUNK (DDIM / BKC)     // 4
#define NTILES (NTOT / BM)      // 64
#define NBLK   (NTILES * (NTILES + 1) / 2)   // 2080

#define ASTG   16384            // A stage: 8 rowblocks x 4 ksteps x 512B
#define BSTG   16384            // B stage: 16 colblocks x 4 ksteps x 256B

// dynamic smem byte offsets (3 stages each)
#define SM_A0   0
#define SM_B0   (3 * ASTG)      // 49152
#define SM_SQI  (6 * ASTG)      // 98304  (holds -sq*c4)
#define SM_SQJ  (SM_SQI + 512)
#define SM_RED  (SM_SQI + 1024)
#define SM_AUX  (SM_RED + 1024) // 8 doubles (wred) + c4
#define SMEM_BYTES (SM_AUX + 128)   // 100480 -> 2 CTAs/SM

__device__ __half   g_convA[NTOT * DDIM];  // A-fragment order, 4 MB
__device__ __half   g_convB[NTOT * DDIM];  // B-fragment order, 4 MB
__device__ float    g_sq[NTOT];
__device__ float    g_colsum[DDIM];
__device__ double   g_ssum;
__device__ double   g_acc;
__device__ unsigned g_done;

// ---------------------------------------------------------------------------
__device__ __forceinline__ float ex2f(float x) {
    float r; asm("ex2.approx.ftz.f32 %0, %1;" : "=f"(r) : "f"(x)); return r;
}
__device__ __forceinline__ uint32_t smem_u32(const void* p) {
    uint32_t a;
    asm("{ .reg .u64 t; cvta.to.shared.u64 t, %1; cvt.u32.u64 %0, t; }"
        : "=r"(a) : "l"(p));
    return a;
}
__device__ __forceinline__ void cp16(uint32_t dst, const void* src) {
    asm volatile("cp.async.cg.shared.global [%0], [%1], 16;"
                 :: "r"(dst), "l"(src));
}
__device__ __forceinline__ void cp_commit() {
    asm volatile("cp.async.commit_group;" ::: "memory");
}
template <int N>
__device__ __forceinline__ void cp_wait() {
    asm volatile("cp.async.wait_group %0;" :: "n"(N) : "memory");
}
__device__ __forceinline__ void mma_f16(float c[4], const uint4 a,
                                        const uint2 b) {
    asm volatile(
        "mma.sync.aligned.m16n8k16.row.col.f32.f16.f16.f32 "
        "{%0,%1,%2,%3},{%4,%5,%6,%7},{%8,%9},{%0,%1,%2,%3};"
        : "+f"(c[0]), "+f"(c[1]), "+f"(c[2]), "+f"(c[3])
        : "r"(a.x), "r"(a.y), "r"(a.z), "r"(a.w), "r"(b.x), "r"(b.y));
}
__device__ __forceinline__ uint32_t pack_h2(float lo, float hi) {
    __half2 h = __floats2half2_rn(lo, hi);
    return *(uint32_t*)&h;
}

// ---------------------------------------------------------------------------
__global__ void init_kernel() {
    int t = threadIdx.x;
    if (t < DDIM) g_colsum[t] = 0.0f;
    if (t == 0) { g_acc = 0.0; g_ssum = 0.0; g_done = 0u; }
}

// Fused prep+permute: block RB owns 16 rows. Stages rows in smem, computes
// row sumsq + colsum partials + ssum, writes fp16 fragment-ordered copies.
#define PSTR 260   // padded row stride (floats): conflict-free column walks
__global__ void prep_permute_kernel(const float* __restrict__ src,
                                    const float* __restrict__ tgt) {
    __shared__ float rows[16 * PSTR];
    __shared__ float wsq[16];
    const int tid  = threadIdx.x;
    const int w    = tid >> 5;
    const int lane = tid & 31;
    const int RB   = blockIdx.x;            // 0..511
    const int r0   = RB * 16;
    const float* base = (r0 < NS) ? (src + (size_t)r0 * DDIM)
                                  : (tgt + (size_t)(r0 - NS) * DDIM);

    // load 16 rows (1024 float4, coalesced)
    #pragma unroll
    for (int i = 0; i < 4; i++) {
        int u = tid + i * 256;
        int r = u >> 6, c4i = u & 63;
        float4 v = *(const float4*)(base + (size_t)r * DDIM + c4i * 4);
        float* d = &rows[r * PSTR + c4i * 4];
        d[0] = v.x; d[1] = v.y; d[2] = v.z; d[3] = v.w;
    }
    __syncthreads();

    // sumsq: warp w -> rows w and w+8
    #pragma unroll
    for (int rr = 0; rr < 2; rr++) {
        int r = w + rr * 8;
        float s = 0.0f;
        #pragma unroll
        for (int i = 0; i < 8; i++) {
            float x = rows[r * PSTR + lane + i * 32];
            s += x * x;
        }
        #pragma unroll
        for (int o = 16; o > 0; o >>= 1) s += __shfl_xor_sync(0xFFFFFFFFu, s, o);
        if (lane == 0) { g_sq[r0 + r] = s; wsq[r] = s; }
    }

    // colsum partial: thread t sums column t over 16 rows
    {
        float cs = 0.0f;
        #pragma unroll
        for (int r = 0; r < 16; r++) cs += rows[r * PSTR + tid];
        atomicAdd(&g_colsum[tid], cs);
    }
    __syncthreads();
    if (tid == 0) {
        float tot = 0.0f;
        #pragma unroll
        for (int i = 0; i < 16; i++) tot += wsq[i];
        atomicAdd(&g_ssum, (double)tot);
    }

    // A-fragment write: 512 uint4 units for rowblock RB
    #pragma unroll
    for (int i = 0; i < 2; i++) {
        int o  = tid + i * 256;
        int KS = o >> 5, ln = o & 31;
        int g  = ln >> 2, t4 = ln & 3;
        int k  = KS * 16 + t4 * 2;
        const float* p0 = &rows[g * PSTR];
        const float* p1 = &rows[(g + 8) * PSTR];
        uint4 v;
        v.x = pack_h2(p0[k],     p0[k + 1]);
        v.y = pack_h2(p1[k],     p1[k + 1]);
        v.z = pack_h2(p0[k + 8], p0[k + 9]);
        v.w = pack_h2(p1[k + 8], p1[k + 9]);
        *(uint4*)((char*)g_convA + (size_t)RB * 8192 + o * 16) = v;
    }
    // B-fragment write: colblocks 2*RB, 2*RB+1 (1024 uint2 units)
    #pragma unroll
    for (int i = 0; i < 4; i++) {
        int o   = tid + i * 256;
        int CBl = o >> 9, rem = o & 511;
        int KS  = rem >> 5, ln = rem & 31;
        int g   = ln >> 2, t4 = ln & 3;
        int r   = CBl * 8 + g;
        int k   = KS * 16 + t4 * 2;
        const float* p = &rows[r * PSTR];
        uint2 v;
        v.x = pack_h2(p[k],     p[k + 1]);
        v.y = pack_h2(p[k + 8], p[k + 9]);
        *(uint2*)((char*)g_convB + (size_t)(RB * 2 + CBl) * 4096 + rem * 8) = v;
    }
}

// ---------------------------------------------------------------------------
// Fused tile kernel: inline c4, fp16 fragment smem, 3-stage cp.async,
// all-fp32 epilogue with 5 accumulator chains.
__global__ void __launch_bounds__(256, 2)
mmd_kernel(float* __restrict__ out) {
    // triangular decode: idx -> (ti, tj), ti <= tj
    int idx = blockIdx.x;
    int ti = (int)((129.0 - sqrt(129.0 * 129.0 - 8.0 * (double)idx)) * 0.5);
    if (ti > NTILES - 1) ti = NTILES - 1;
    while (ti > 0 && idx < ti * NTILES - ti * (ti - 1) / 2) ti--;
    while (idx >= (ti + 1) * NTILES - (ti + 1) * ti / 2) ti++;
    const int tj = ti + (idx - (ti * NTILES - ti * (ti - 1) / 2));

    extern __shared__ char smem[];
    const uint32_t sbase = smem_u32(smem);
    float*  sqi  = (float*)(smem + SM_SQI);   // -sq_i * c4
    float*  sqj  = (float*)(smem + SM_SQJ);   // -sq_j * c4
    float*  red  = (float*)(smem + SM_RED);
    double* wred = (double*)(smem + SM_AUX);
    float*  sc4  = (float*)(smem + SM_AUX + 64);

    const int tid  = threadIdx.x;
    const int wid  = tid >> 5;
    const int lane = tid & 31;
    const int g    = lane >> 2;
    const int t4   = lane & 3;
    const int wm   = wid & 1;
    const int wn   = wid >> 1;

    const int i0 = ti * BM;
    const int j0 = tj * BM;
    const int Rb = ti * 8;
    const int Cb = tj * 16;

    // prologue cp.async first (no c4 dependency)
    #pragma unroll
    for (int c = 0; c < 2; c++) {
        #pragma unroll
        for (int l = 0; l < 4; l++) {
            int ia = tid + l * 256;
            cp16(sbase + SM_A0 + c * ASTG + ia * 16,
                 (const char*)g_convA + (size_t)(Rb + (ia >> 7)) * 8192
                     + (c * 4 + ((ia >> 5) & 3)) * 512 + (ia & 31) * 16);
            cp16(sbase + SM_B0 + c * BSTG + ia * 16,
                 (const char*)g_convB + (size_t)(Cb + (ia >> 6)) * 4096
                     + (c * 4 + ((ia >> 4) & 3)) * 256 + (ia & 15) * 16);
        }
        cp_commit();
    }

    // inline c4 = log2e / (bw * 16), bw via O(nD) identity (overlaps cp.async)
    {
        float c = g_colsum[tid];
        double v = (double)c * (double)c;
        #pragma unroll
        for (int o = 16; o > 0; o >>= 1)
            v += __shfl_xor_sync(0xFFFFFFFFu, v, o);
        if (lane == 0) wred[wid] = v;
        __syncthreads();
        if (tid == 0) {
            double V = 0.0;
            #pragma unroll
            for (int i = 0; i < 8; i++) V += wred[i];
            double S      = g_ssum;
            double n      = (double)NTOT;
            double sum_l2 = 2.0 * n * S - 2.0 * V;
            double bw     = sum_l2 / (n * n - n);
            bw /= 4.0;                               // KERNEL_MUL^(NUM//2)
            sc4[0] = (float)(1.4426950408889634 / (bw * 16.0));
        }
        __syncthreads();
    }
    const float c4 = sc4[0];
    const float c2 = 2.0f * c4;
    if (tid < 128) sqi[tid]       = -g_sq[i0 + tid] * c4;
    else           sqj[tid - 128] = -g_sq[j0 + tid - 128] * c4;

    float acc[4][4][4];
    #pragma unroll
    for (int a = 0; a < 4; a++)
        #pragma unroll
        for (int b = 0; b < 4; b++)
            #pragma unroll
            for (int f = 0; f < 4; f++) acc[a][b][f] = 0.0f;

    int st_c = 0, st_p = 2;
    #pragma unroll 1
    for (int c = 0; c < NCHUNK; c++) {
        if (c + 2 < NCHUNK) {
            const int cc = c + 2;
            #pragma unroll
            for (int l = 0; l < 4; l++) {
                int ia = tid + l * 256;
                cp16(sbase + SM_A0 + st_p * ASTG + ia * 16,
                     (const char*)g_convA + (size_t)(Rb + (ia >> 7)) * 8192
                         + (cc * 4 + ((ia >> 5) & 3)) * 512 + (ia & 31) * 16);
                cp16(sbase + SM_B0 + st_p * BSTG + ia * 16,
                     (const char*)g_convB + (size_t)(Cb + (ia >> 6)) * 4096
                         + (cc * 4 + ((ia >> 4) & 3)) * 256 + (ia & 15) * 16);
            }
            cp_commit();
            cp_wait<2>();
        } else if (c + 1 < NCHUNK) {
            cp_wait<1>();
        } else {
            cp_wait<0>();
        }
        __syncthreads();

        const char* As = smem + SM_A0 + st_c * ASTG;
        const char* Bs = smem + SM_B0 + st_c * BSTG;

        #pragma unroll
        for (int s = 0; s < 4; s++) {
            uint4 af[4];
            uint2 bf[4];
            #pragma unroll
            for (int ma = 0; ma < 4; ma++)
                af[ma] = *(const uint4*)(As + (wm * 4 + ma) * 2048 + s * 512
                                            + lane * 16);
            #pragma unroll
            for (int nb = 0; nb < 4; nb++)
                bf[nb] = *(const uint2*)(Bs + (wn * 4 + nb) * 1024 + s * 256
                                            + lane * 8);
            #pragma unroll
            for (int ma = 0; ma < 4; ma++)
                #pragma unroll
                for (int nb = 0; nb < 4; nb++)
                    mma_f16(acc[ma][nb], af[ma], bf[nb]);
        }
        __syncthreads();

        st_c = (st_c == 2) ? 0 : st_c + 1;
        st_p = (st_p == 2) ? 0 : st_p + 1;
    }

    // --- epilogue: arg = fma(acc, 2c4, -(si+sj)c4); 5 fp32 accumulators ---
    float nsi[4][2], nsj[4][2];
    #pragma unroll
    for (int ma = 0; ma < 4; ma++) {
        nsi[ma][0] = sqi[wm * 64 + ma * 16 + g];
        nsi[ma][1] = sqi[wm * 64 + ma * 16 + g + 8];
    }
    #pragma unroll
    for (int nb = 0; nb < 4; nb++) {
        nsj[nb][0] = sqj[wn * 32 + nb * 8 + 2 * t4];
        nsj[nb][1] = sqj[wn * 32 + nb * 8 + 2 * t4 + 1];
    }

    float p1 = 0.0f, p2s = 0.0f, p3 = 0.0f, p4 = 0.0f, p5 = 0.0f;
    #pragma unroll
    for (int ma = 0; ma < 4; ma++) {
        #pragma unroll
        for (int nb = 0; nb < 4; nb++) {
            const float* a = acc[ma][nb];
            #pragma unroll
            for (int f = 0; f < 4; f++) {
                float ns  = nsi[ma][f >> 1] + nsj[nb][f & 1];
                float u   = ex2f(fmaf(a[f], c2, ns));
                float u2  = u * u;
                float u4  = u2 * u2;
                float u8  = u4 * u4;
                p1 += u; p2s += u2; p3 += u4; p4 += u8;
                p5 = fmaf(u8, u8, p5);
            }
        }
    }
    float part = (p1 + p2s) + (p3 + p4) + p5;

    float w  = (ti == tj) ? 1.0f : 2.0f;
    float sg = ((ti < NTILES / 2) == (tj < NTILES / 2)) ? 1.0f : -1.0f;
    part *= w * sg;

    red[tid] = part;
    __syncthreads();
    #pragma unroll
    for (int s = 128; s > 0; s >>= 1) {
        if (tid < s) red[tid] += red[tid + s];
        __syncthreads();
    }
    if (tid == 0) {
        atomicAdd(&g_acc, (double)red[0]);
        __threadfence();
        unsigned old = atomicAdd(&g_done, 1u);
        if (old == NBLK - 1) {
            double v = atomicAdd(&g_acc, 0.0);   // atomic read after fence
            out[0] = (float)(v / ((double)NS * (double)NS));
        }
    }
}

// ---------------------------------------------------------------------------
extern "C" void kernel_launch(void* const* d_in, const int* in_sizes, int n_in,
                              void* d_out, int out_size) {
    const float* src = (const float*)d_in[0];
    const float* tgt = (const float*)d_in[1];
    float* out = (float*)d_out;

    cudaFuncSetAttribute(mmd_kernel,
                         cudaFuncAttributeMaxDynamicSharedMemorySize, SMEM_BYTES);

    init_kernel<<<1, 256>>>();
    prep_permute_kernel<<<NTOT / 16, 256>>>(src, tgt);
    mmd_kernel<<<NBLK, 256, SMEM_BYTES>>>(out);
}

// round 14
// speedup vs baseline: 1.1568x; 1.1568x over previous
#include <cuda_runtime.h>
#include <cuda_fp16.h>
#include <cstdint>

// ---------------------------------------------------------------------------
// MMD loss via mma.sync fp16 gram (fp32 accum) + fused fp32 gaussian epilogue
//   loss = (1/ns^2) * sum_{i,j} s_i s_j K_ij
//   K_ij = u + u^2 + u^4 + u^8 + u^16,  u = 2^(-l2_ij*c4), c4 = log2e/(bw*16)
//   l2_ij = sq_i + sq_j - 2 g_ij ; bandwidth via O(nD) identity.
// R8-proven hot kernels (mmd/prep/permute verbatim); 3 launches:
//   prep -> permute(+c4 finalize) -> mmd(+writeout, +state reset for replay).
// State reset: __device__ globals are zero-init at load; the last mmd block
// zeroes g_colsum/g_ssum/g_acc/g_done after writeout so graph replays are
// deterministic without an init kernel.
// Symmetry: triangular grid (2080 CTAs), off-diagonal tiles weight 2.
// ---------------------------------------------------------------------------

#define NS     4096
#define DDIM   256
#define NTOT   8192
#define BM     128
#define BKC    64
#define NCHUNK (DDIM / BKC)     // 4
#define NTILES (NTOT / BM)      // 64
#define NBLK   (NTILES * (NTILES + 1) / 2)   // 2080

#define ASTG   16384            // A stage: 8 rowblocks x 4 ksteps x 512B
#define BSTG   16384            // B stage: 16 colblocks x 4 ksteps x 256B

// smem byte offsets (3 stages each)
#define SM_A0   0
#define SM_B0   (3 * ASTG)      // 49152
#define SM_SQI  (6 * ASTG)      // 98304
#define SM_SQJ  (SM_SQI + 512)
#define SM_RED  (SM_SQI + 1024)
#define SMEM_BYTES (SM_SQI + 2048)   // 100352 -> 2 CTAs/SM

__device__ __half   g_convA[NTOT * DDIM];  // A-fragment order, 4 MB
__device__ __half   g_convB[NTOT * DDIM];  // B-fragment order, 4 MB
__device__ float    g_sq[NTOT];
__device__ float    g_colsum[DDIM];        // zero-init; reset by mmd tail
__device__ double   g_ssum;                // zero-init; reset by mmd tail
__device__ double   g_acc;                 // zero-init; reset by mmd tail
__device__ float    g_c4;
__device__ unsigned g_done;                // zero-init; reset by mmd tail

// ---------------------------------------------------------------------------
__device__ __forceinline__ float ex2f(float x) {
    float r; asm("ex2.approx.ftz.f32 %0, %1;" : "=f"(r) : "f"(x)); return r;
}
__device__ __forceinline__ uint32_t smem_u32(const void* p) {
    uint32_t a;
    asm("{ .reg .u64 t; cvta.to.shared.u64 t, %1; cvt.u32.u64 %0, t; }"
        : "=r"(a) : "l"(p));
    return a;
}
__device__ __forceinline__ void cp16(uint32_t dst, const void* src) {
    asm volatile("cp.async.cg.shared.global [%0], [%1], 16;"
                 :: "r"(dst), "l"(src));
}
__device__ __forceinline__ void cp_commit() {
    asm volatile("cp.async.commit_group;" ::: "memory");
}
template <int N>
__device__ __forceinline__ void cp_wait() {
    asm volatile("cp.async.wait_group %0;" :: "n"(N) : "memory");
}
__device__ __forceinline__ void mma_f16(float c[4], const uint4 a,
                                        const uint2 b) {
    asm volatile(
        "mma.sync.aligned.m16n8k16.row.col.f32.f16.f16.f32 "
        "{%0,%1,%2,%3},{%4,%5,%6,%7},{%8,%9},{%0,%1,%2,%3};"
        : "+f"(c[0]), "+f"(c[1]), "+f"(c[2]), "+f"(c[3])
        : "r"(a.x), "r"(a.y), "r"(a.z), "r"(a.w), "r"(b.x), "r"(b.y));
}
__device__ __forceinline__ const float* srow(const float* __restrict__ src,
                                             const float* __restrict__ tgt,
                                             int row) {
    return (row < NS) ? (src + (size_t)row * DDIM)
                      : (tgt + (size_t)(row - NS) * DDIM);
}
__device__ __forceinline__ uint32_t pack_h2(float lo, float hi) {
    __half2 h = __floats2half2_rn(lo, hi);
    return *(uint32_t*)&h;
}

// ---------------------------------------------------------------------------
// prep: sumsq per row + colsums + total sumsq (reads raw fp32 src/tgt).
// (R8 verbatim)
__global__ void prep_kernel(const float* __restrict__ src,
                            const float* __restrict__ tgt) {
    const int tid  = threadIdx.x;
    const int w    = tid >> 5;
    const int lane = tid & 31;
    const int b    = blockIdx.x;
    const float* base = (b < 128) ? (src + (size_t)b * 32 * DDIM)
                                  : (tgt + (size_t)(b - 128) * 32 * DDIM);
    __shared__ float wsum[8];

    float mysq = 0.0f;
    #pragma unroll
    for (int it = 0; it < 4; it++) {
        int r = it * 8 + w;
        const float* p = base + (size_t)r * DDIM;
        float4 a = *(const float4*)(p + lane * 8);
        float4 c = *(const float4*)(p + lane * 8 + 4);
        float s = a.x*a.x + a.y*a.y + a.z*a.z + a.w*a.w
                + c.x*c.x + c.y*c.y + c.z*c.z + c.w*c.w;
        #pragma unroll
        for (int o = 16; o > 0; o >>= 1) s += __shfl_xor_sync(0xFFFFFFFFu, s, o);
        if (lane == 0) { g_sq[b * 32 + r] = s; mysq += s; }
    }
    if (lane == 0) wsum[w] = mysq;

    float cs = 0.0f;
    #pragma unroll 8
    for (int r = 0; r < 32; r++) cs += base[(size_t)r * DDIM + tid];
    atomicAdd(&g_colsum[tid], cs);

    __syncthreads();
    if (tid == 0) {
        float tot = 0.0f;
        #pragma unroll
        for (int i = 0; i < 8; i++) tot += wsum[i];
        atomicAdd(&g_ssum, (double)tot);
    }
}

// permute: c4 finalize (every block; block 0 publishes g_c4), then the
// R8-verbatim fp16 fragment-ordered copies (no scale folding).
// blocks [0,1024): A. blocks [1024,3072): B.
__global__ void permute_kernel(const float* __restrict__ src,
                               const float* __restrict__ tgt) {
    __shared__ double wred[8];
    const int tid  = threadIdx.x;
    const int w    = tid >> 5;
    const int lane = tid & 31;

    if (blockIdx.x == 0) {   // publish c4 once (other blocks don't need it)
        float c = g_colsum[tid];
        double v = (double)c * (double)c;
        #pragma unroll
        for (int o = 16; o > 0; o >>= 1)
            v += __shfl_xor_sync(0xFFFFFFFFu, v, o);
        if (lane == 0) wred[w] = v;
        __syncthreads();
        if (tid == 0) {
            double V = 0.0;
            #pragma unroll
            for (int i = 0; i < 8; i++) V += wred[i];
            double S      = g_ssum;
            double n      = (double)NTOT;
            double sum_l2 = 2.0 * n * S - 2.0 * V;
            double bw     = sum_l2 / (n * n - n);
            bw /= 4.0;                               // KERNEL_MUL^(NUM//2)
            g_c4 = (float)(1.4426950408889634 / (bw * 16.0));
        }
    }

    if (blockIdx.x < 1024) {
        int o    = blockIdx.x * 256 + tid;          // 16B unit index
        int RB   = o >> 9;
        int rem  = o & 511;
        int KS   = rem >> 5;
        int ln   = rem & 31;
        int g    = ln >> 2;
        int t4   = ln & 3;
        int r    = RB * 16 + g;
        int k    = KS * 16 + t4 * 2;
        const float* p0 = srow(src, tgt, r);
        const float* p1 = srow(src, tgt, r + 8);
        uint4 v;
        v.x = pack_h2(p0[k],     p0[k + 1]);
        v.y = pack_h2(p1[k],     p1[k + 1]);
        v.z = pack_h2(p0[k + 8], p0[k + 9]);
        v.w = pack_h2(p1[k + 8], p1[k + 9]);
        *(uint4*)((char*)g_convA + (size_t)o * 16) = v;
    } else {
        int o    = (blockIdx.x - 1024) * 256 + tid; // 8B unit index
        int CB   = o >> 9;
        int rem  = o & 511;
        int KS   = rem >> 5;
        int ln   = rem & 31;
        int g    = ln >> 2;
        int t4   = ln & 3;
        int c    = CB * 8 + g;
        int k    = KS * 16 + t4 * 2;
        const float* p = srow(src, tgt, c);
        uint2 v;
        v.x = pack_h2(p[k],     p[k + 1]);
        v.y = pack_h2(p[k + 8], p[k + 9]);
        *(uint2*)((char*)g_convB + (size_t)o * 8) = v;
    }
}

// ---------------------------------------------------------------------------
// Fused tile kernel (R8 verbatim) + last-block writeout & state reset.
__global__ void __launch_bounds__(256, 2)
mmd_kernel(float* __restrict__ out) {
    // triangular decode: idx -> (ti, tj), ti <= tj
    int idx = blockIdx.x;
    int ti = (int)((129.0 - sqrt(129.0 * 129.0 - 8.0 * (double)idx)) * 0.5);
    if (ti > NTILES - 1) ti = NTILES - 1;
    while (ti > 0 && idx < ti * NTILES - ti * (ti - 1) / 2) ti--;
    while (idx >= (ti + 1) * NTILES - (ti + 1) * ti / 2) ti++;
    const int tj = ti + (idx - (ti * NTILES - ti * (ti - 1) / 2));

    extern __shared__ char smem[];
    const uint32_t sbase = smem_u32(smem);
    float* sqi = (float*)(smem + SM_SQI);
    float* sqj = (float*)(smem + SM_SQJ);
    float* red = (float*)(smem + SM_RED);

    const int tid  = threadIdx.x;
    const int wid  = tid >> 5;
    const int lane = tid & 31;
    const int g    = lane >> 2;
    const int t4   = lane & 3;
    const int wm   = wid & 1;
    const int wn   = wid >> 1;

    const int i0 = ti * BM;
    const int j0 = tj * BM;
    const int Rb = ti * 8;
    const int Cb = tj * 16;

    if (tid < 128) sqi[tid]       = g_sq[i0 + tid];
    else           sqj[tid - 128] = g_sq[j0 + tid - 128];

    #pragma unroll
    for (int c = 0; c < 2; c++) {
        #pragma unroll
        for (int l = 0; l < 4; l++) {
            int ia = tid + l * 256;
            cp16(sbase + SM_A0 + c * ASTG + ia * 16,
                 (const char*)g_convA + (size_t)(Rb + (ia >> 7)) * 8192
                     + (c * 4 + ((ia >> 5) & 3)) * 512 + (ia & 31) * 16);
            cp16(sbase + SM_B0 + c * BSTG + ia * 16,
                 (const char*)g_convB + (size_t)(Cb + (ia >> 6)) * 4096
                     + (c * 4 + ((ia >> 4) & 3)) * 256 + (ia & 15) * 16);
        }
        cp_commit();
    }

    float acc[4][4][4];
    #pragma unroll
    for (int a = 0; a < 4; a++)
        #pragma unroll
        for (int b = 0; b < 4; b++)
            #pragma unroll
            for (int f = 0; f < 4; f++) acc[a][b][f] = 0.0f;

    int st_c = 0, st_p = 2;
    #pragma unroll 1
    for (int c = 0; c < NCHUNK; c++) {
        if (c + 2 < NCHUNK) {
            const int cc = c + 2;
            #pragma unroll
            for (int l = 0; l < 4; l++) {
                int ia = tid + l * 256;
                cp16(sbase + SM_A0 + st_p * ASTG + ia * 16,
                     (const char*)g_convA + (size_t)(Rb + (ia >> 7)) * 8192
                         + (cc * 4 + ((ia >> 5) & 3)) * 512 + (ia & 31) * 16);
                cp16(sbase + SM_B0 + st_p * BSTG + ia * 16,
                     (const char*)g_convB + (size_t)(Cb + (ia >> 6)) * 4096
                         + (cc * 4 + ((ia >> 4) & 3)) * 256 + (ia & 15) * 16);
            }
            cp_commit();
            cp_wait<2>();
        } else if (c + 1 < NCHUNK) {
            cp_wait<1>();
        } else {
            cp_wait<0>();
        }
        __syncthreads();

        const char* As = smem + SM_A0 + st_c * ASTG;
        const char* Bs = smem + SM_B0 + st_c * BSTG;

        #pragma unroll
        for (int s = 0; s < 4; s++) {
            uint4 af[4];
            uint2 bf[4];
            #pragma unroll
            for (int ma = 0; ma < 4; ma++)
                af[ma] = *(const uint4*)(As + (wm * 4 + ma) * 2048 + s * 512
                                            + lane * 16);
            #pragma unroll
            for (int nb = 0; nb < 4; nb++)
                bf[nb] = *(const uint2*)(Bs + (wn * 4 + nb) * 1024 + s * 256
                                            + lane * 8);
            #pragma unroll
            for (int ma = 0; ma < 4; ma++)
                #pragma unroll
                for (int nb = 0; nb < 4; nb++)
                    mma_f16(acc[ma][nb], af[ma], bf[nb]);
        }
        __syncthreads();

        st_c = (st_c == 2) ? 0 : st_c + 1;
        st_p = (st_p == 2) ? 0 : st_p + 1;
    }

    // --- epilogue (R8 verbatim) ---
    const float c4 = g_c4;
    float si[4][2], sj[4][2];
    #pragma unroll
    for (int ma = 0; ma < 4; ma++) {
        si[ma][0] = sqi[wm * 64 + ma * 16 + g];
        si[ma][1] = sqi[wm * 64 + ma * 16 + g + 8];
    }
    #pragma unroll
    for (int nb = 0; nb < 4; nb++) {
        sj[nb][0] = sqj[wn * 32 + nb * 8 + 2 * t4];
        sj[nb][1] = sqj[wn * 32 + nb * 8 + 2 * t4 + 1];
    }

    float part = 0.0f;
    #pragma unroll
    for (int ma = 0; ma < 4; ma++) {
        #pragma unroll
        for (int nb = 0; nb < 4; nb++) {
            #pragma unroll
            for (int f = 0; f < 4; f++) {
                float nl2 = 2.0f * acc[ma][nb][f] - si[ma][f >> 1] - sj[nb][f & 1];
                float u   = ex2f(nl2 * c4);
                float u2  = u  * u;
                float u4  = u2 * u2;
                float u8  = u4 * u4;
                float u16 = u8 * u8;
                part += (u + u2) + (u4 + u8) + u16;
            }
        }
    }

    float w  = (ti == tj) ? 1.0f : 2.0f;
    float sg = ((ti < NTILES / 2) == (tj < NTILES / 2)) ? 1.0f : -1.0f;
    part *= w * sg;

    red[tid] = part;
    __syncthreads();
    #pragma unroll
    for (int s = 128; s > 0; s >>= 1) {
        if (tid < s) red[tid] += red[tid + s];
        __syncthreads();
    }
    if (tid == 0) {
        atomicAdd(&g_acc, (double)red[0]);
        __threadfence();
        unsigned old = atomicAdd(&g_done, 1u);
        if (old == NBLK - 1) {
            // last block: writeout, then reset state for the next graph replay
            double v = atomicAdd(&g_acc, 0.0);   // atomic read after fence
            out[0] = (float)(v / ((double)NS * (double)NS));
            #pragma unroll 8
            for (int i = 0; i < DDIM; i++) g_colsum[i] = 0.0f;
            g_ssum = 0.0;
            g_acc  = 0.0;
            __threadfence();
            g_done = 0u;
        }
    }
}

// ---------------------------------------------------------------------------
extern "C" void kernel_launch(void* const* d_in, const int* in_sizes, int n_in,
                              void* d_out, int out_size) {
    const float* src = (const float*)d_in[0];
    const float* tgt = (const float*)d_in[1];
    float* out = (float*)d_out;

    cudaFuncSetAttribute(mmd_kernel,
                         cudaFuncAttributeMaxDynamicSharedMemorySize, SMEM_BYTES);

    prep_kernel<<<256, 256>>>(src, tgt);
    permute_kernel<<<3072, 256>>>(src, tgt);
    mmd_kernel<<<NBLK, 256, SMEM_BYTES>>>(out);
}